// round 12
// baseline (speedup 1.0000x reference)
#include <cuda_runtime.h>
#include <cuda.h>
#include <cuda_fp16.h>
#include <math.h>
#include <stdint.h>

// ---------------- problem shape ----------------
#define BDIM 8192
#define IDIM 1024
#define ODIM 1024
#define ND   9
#define K9   (IDIM * ND)       // 9216

// ---------------- GEMM tiling ----------------
#define BM 128
#define BN 256
#define KB 64
#define NKB (K9 / KB)          // 144
#define NSTG 3
#define A_ST 16384             // 128 x 64 fp16
#define B_ST 32768             // 256 x 64 fp16
#define STG_BYTES (A_ST + B_ST)                  // 49152
#define SM_STAGE 1024
#define SMEM_BYTES (SM_STAGE + NSTG * STG_BYTES) // 148480
#define NTHREADS 544           // 16 consumer warps + 1 producer warp

// operand scaling (keeps fp16 operands in normal range)
#define SCALE_A 64.0f
#define SCALE_B 4096.0f
#define SCALE_OUT (1.0f / (SCALE_A * SCALE_B))

// ---------------- static device buffers ----------------
__device__ __half g_A[(size_t)BDIM * K9];   // [b][k], k = d*1024+i, scaled x64
__device__ __half g_B[(size_t)ODIM * K9];   // [o][k] (transposed!), scaled x4096

// ---------------- PTX helpers ----------------
__device__ __forceinline__ uint32_t smem_u32(const void* p) {
    uint32_t a;
    asm("{ .reg .u64 t; cvta.to.shared.u64 t, %1; cvt.u32.u64 %0, t; }" : "=r"(a) : "l"(p));
    return a;
}
__device__ __forceinline__ void mbar_init(uint32_t m, uint32_t cnt) {
    asm volatile("mbarrier.init.shared.b64 [%0], %1;" :: "r"(m), "r"(cnt) : "memory");
}
__device__ __forceinline__ void mbar_expect_tx(uint32_t m, uint32_t bytes) {
    asm volatile("mbarrier.arrive.expect_tx.shared.b64 _, [%0], %1;" :: "r"(m), "r"(bytes) : "memory");
}
__device__ __forceinline__ void mbar_arrive(uint32_t m) {
    asm volatile("mbarrier.arrive.shared.b64 _, [%0];" :: "r"(m) : "memory");
}
__device__ __forceinline__ void mbar_wait(uint32_t m, uint32_t parity) {
    asm volatile(
        "{\n\t.reg .pred P;\n"
        "LW_%=:\n\t"
        "mbarrier.try_wait.parity.acquire.cta.shared::cta.b64 P, [%0], %1, 0x989680;\n\t"
        "@P bra.uni LD_%=;\n\t"
        "bra.uni LW_%=;\n"
        "LD_%=:\n\t}"
        :: "r"(m), "r"(parity) : "memory");
}
__device__ __forceinline__ void tma_2d(uint32_t dst, const void* map, int x, int y, uint32_t mbar) {
    asm volatile(
        "cp.async.bulk.tensor.2d.shared::cta.global.tile.mbarrier::complete_tx::bytes "
        "[%0], [%1, {%2, %3}], [%4];"
        :: "r"(dst), "l"(map), "r"(x), "r"(y), "r"(mbar) : "memory");
}
__device__ __forceinline__ void ldsm4(uint32_t* r, uint32_t a) {
    asm volatile("ldmatrix.sync.aligned.m8n8.x4.shared.b16 {%0,%1,%2,%3}, [%4];"
                 : "=r"(r[0]), "=r"(r[1]), "=r"(r[2]), "=r"(r[3]) : "r"(a));
}
__device__ __forceinline__ void mma16816(float* d, const uint32_t* a, const uint32_t* b) {
    asm volatile(
        "mma.sync.aligned.m16n8k16.row.col.f32.f16.f16.f32 "
        "{%0,%1,%2,%3}, {%4,%5,%6,%7}, {%8,%9}, {%0,%1,%2,%3};"
        : "+f"(d[0]), "+f"(d[1]), "+f"(d[2]), "+f"(d[3])
        : "r"(a[0]), "r"(a[1]), "r"(a[2]), "r"(a[3]), "r"(b[0]), "r"(b[1]));
}
// SW128 swizzle (matches CU_TENSOR_MAP_SWIZZLE_128B for 128B rows)
__device__ __forceinline__ uint32_t swz(uint32_t off) { return off ^ ((off >> 3) & 0x70); }

// ---------------- prep kernels ----------------
__global__ void prep_basis_kernel(const float* __restrict__ x) {
    int idx = blockIdx.x * blockDim.x + threadIdx.x;
    int b = idx >> 10;
    int i = idx & 1023;
    const float S = 5.1231056256176605f;    // sqrt(17)+1
    const float PIQ = 0.7511255444649425f;  // pi^-1/4
    const float SQ2 = 1.4142135623730951f;
    const float ha[9] = {0.f, 0.f, 1.0f, 0.8164965809f, 0.7071067812f,
                         0.6324555320f, 0.5773502692f, 0.5345224838f, 0.5f};
    const float hb[9] = {0.f, 0.f, 0.7071067812f, 0.8164965809f, 0.8660254038f,
                         0.8944271910f, 0.9128709292f, 0.9258200998f, 0.9354143467f};
    float t = tanhf(x[idx]) * S;
    float g = expf(-0.5f * t * t);
    float h[ND];
    h[0] = PIQ * g;
    h[1] = SQ2 * t * h[0];
#pragma unroll
    for (int d = 2; d < ND; ++d) h[d] = ha[d] * t * h[d - 1] - hb[d] * h[d - 2];
    size_t base = (size_t)b * K9 + i;
#pragma unroll
    for (int d = 0; d < ND; ++d)
        g_A[base + (size_t)d * 1024] = __float2half_rn(h[d] * SCALE_A);
}

// c[i][o][d] -> g_B[o][d*1024+i], coalesced both sides via 32x32x9 smem tile
__global__ __launch_bounds__(256)
void prep_w_kernel(const float* __restrict__ c) {
    __shared__ float s[32][289];           // 289 % 32 == 1 -> conflict-free phase 2
    int i0 = blockIdx.x * 32;
    int o0 = blockIdx.y * 32;
    // phase 1: 32 rows x 288 floats, float4 global loads, scalar smem stores
    for (int j = threadIdx.x; j < 32 * 72; j += 256) {
        int i = j / 72, q = j - (j / 72) * 72;
        float4 v = *(const float4*)(c + ((size_t)(i0 + i) * 1024 + o0) * 9 + q * 4);
        s[i][q * 4 + 0] = v.x; s[i][q * 4 + 1] = v.y;
        s[i][q * 4 + 2] = v.z; s[i][q * 4 + 3] = v.w;
    }
    __syncthreads();
    // phase 2: col = o*9+d; warp lanes sweep i (contiguous 64B half writes)
    int lane = threadIdx.x & 31, w = threadIdx.x >> 5;
    for (int col = w; col < 288; col += 8) {
        int o = col / 9, d = col - o * 9;
        g_B[(size_t)(o0 + o) * K9 + d * 1024 + i0 + lane] =
            __float2half_rn(s[lane][col] * SCALE_B);
    }
}

// ---------------- TMA-fed HMMA GEMM ----------------
// 17 warps: 0-15 consumers (4x4 warp grid, warp tile 32x64), warp 16 = TMA producer.
__global__ __launch_bounds__(NTHREADS, 1)
void kan_hmma_kernel(const __grid_constant__ CUtensorMap tmA,
                     const __grid_constant__ CUtensorMap tmB,
                     float* __restrict__ y) {
    extern __shared__ __align__(1024) char smem[];
    const uint32_t sb = smem_u32(smem);
    const int tid = threadIdx.x;
    const int wid = tid >> 5;
    const int lane = tid & 31;
    const int rowBase = blockIdx.y * BM;
    const int colBase = blockIdx.x * BN;
    // barriers: full[s] at sb+0,8,16 ; empty[s] at sb+24,32,40
    const uint32_t FULL = sb, EMPTY = sb + 24;

    if (tid == 0) {
        for (int s = 0; s < NSTG; ++s) {
            mbar_init(FULL + s * 8, 1);      // producer expect_tx arrival
            mbar_init(EMPTY + s * 8, 512);   // all consumer threads arrive
        }
    }
    __syncthreads();

    if (wid == 16) {
        // ---- producer ----
        if (lane == 0) {
            uint32_t stg = 0, pe = 1;
            for (int kb = 0; kb < NKB; ++kb) {
                mbar_wait(EMPTY + stg * 8, pe);
                uint32_t fb = FULL + stg * 8;
                mbar_expect_tx(fb, STG_BYTES);
                uint32_t s0 = sb + SM_STAGE + stg * STG_BYTES;
                tma_2d(s0,        &tmA, kb * KB, rowBase, fb);
                tma_2d(s0 + A_ST, &tmB, kb * KB, colBase, fb);
                if (++stg == NSTG) { stg = 0; pe ^= 1; }
            }
        }
        return;
    }

    // ---- consumers ----
    const int wm = wid & 3;          // 4 warp-rows of 32
    const int wn = wid >> 2;         // 4 warp-cols of 64

    float acc[2][8][4];
#pragma unroll
    for (int a = 0; a < 2; ++a)
#pragma unroll
        for (int b = 0; b < 8; ++b)
#pragma unroll
            for (int q = 0; q < 4; ++q) acc[a][b][q] = 0.0f;

    // precomputed intra-tile ldsm lane offsets
    // A: mat0 m0-7/k0-7, mat1 m8-15/k0-7, mat2 m0-7/k8-15, mat3 m8-15/k8-15
    const uint32_t aRow = wm * 32 + (lane & 15);
    const uint32_t aCol = (lane >> 4) * 16;
    // B (non-trans on [n][k]): mat0 n0-7/k0-7, mat1 n0-7/k8-15, mat2 n8-15/k0-7, mat3 n8-15/k8-15
    const uint32_t q2 = lane >> 3;
    const uint32_t bRow = wn * 64 + (lane & 7) + (q2 >> 1) * 8;
    const uint32_t bCol = (q2 & 1) * 16;

    uint32_t stg = 0, pf = 0;
    for (int kb = 0; kb < NKB; ++kb) {
        mbar_wait(FULL + stg * 8, pf);
        const uint32_t sA = sb + SM_STAGE + stg * STG_BYTES;
        const uint32_t sB = sA + A_ST;

#pragma unroll
        for (int ks = 0; ks < 4; ++ks) {
            uint32_t aF[2][4];
#pragma unroll
            for (int mt = 0; mt < 2; ++mt)
                ldsm4(aF[mt], sA + swz((aRow + mt * 16) * 128 + ks * 32 + aCol));
#pragma unroll
            for (int ng = 0; ng < 4; ++ng) {
                uint32_t bF[4];
                ldsm4(bF, sB + swz((bRow + ng * 16) * 128 + ks * 32 + bCol));
#pragma unroll
                for (int mt = 0; mt < 2; ++mt) {
                    mma16816(acc[mt][ng * 2],     aF[mt], &bF[0]);
                    mma16816(acc[mt][ng * 2 + 1], aF[mt], &bF[2]);
                }
            }
        }
        mbar_arrive(EMPTY + stg * 8);
        if (++stg == NSTG) { stg = 0; pf ^= 1; }
    }

    // epilogue: scale back, store
    const float SC = SCALE_OUT;
#pragma unroll
    for (int mt = 0; mt < 2; ++mt) {
#pragma unroll
        for (int n8 = 0; n8 < 8; ++n8) {
            int r0 = rowBase + wm * 32 + mt * 16 + (lane >> 2);
            int c0 = colBase + wn * 64 + n8 * 8 + (lane & 3) * 2;
            *(float2*)&y[(size_t)r0 * ODIM + c0] =
                make_float2(acc[mt][n8][0] * SC, acc[mt][n8][1] * SC);
            *(float2*)&y[(size_t)(r0 + 8) * ODIM + c0] =
                make_float2(acc[mt][n8][2] * SC, acc[mt][n8][3] * SC);
        }
    }
}

// ---------------- host ----------------
typedef CUresult (*PFN_encodeTiled)(CUtensorMap*, CUtensorMapDataType, cuuint32_t, void*,
                                    const cuuint64_t*, const cuuint64_t*, const cuuint32_t*,
                                    const cuuint32_t*, CUtensorMapInterleave, CUtensorMapSwizzle,
                                    CUtensorMapL2promotion, CUtensorMapFloatOOBfill);

static void encode_map(PFN_encodeTiled enc, CUtensorMap* m, void* ptr,
                       uint64_t d0, uint64_t d1, uint32_t b0, uint32_t b1) {
    cuuint64_t dims[2] = {d0, d1};
    cuuint64_t strides[1] = {d0 * sizeof(__half)};
    cuuint32_t box[2] = {b0, b1};
    cuuint32_t es[2] = {1, 1};
    enc(m, CU_TENSOR_MAP_DATA_TYPE_FLOAT16, 2, ptr, dims, strides, box, es,
        CU_TENSOR_MAP_INTERLEAVE_NONE, CU_TENSOR_MAP_SWIZZLE_128B,
        CU_TENSOR_MAP_L2_PROMOTION_L2_128B, CU_TENSOR_MAP_FLOAT_OOB_FILL_NONE);
}

extern "C" void kernel_launch(void* const* d_in, const int* in_sizes, int n_in,
                              void* d_out, int out_size) {
    const float* x = (const float*)d_in[0];
    const float* c = (const float*)d_in[1];
    if (n_in >= 2 && in_sizes[0] == K9 * ODIM) {   // coeffs first? swap
        const float* t = x; x = c; c = t;
    }
    float* y = (float*)d_out;

    prep_w_kernel<<<dim3(IDIM / 32, ODIM / 32), 256>>>(c);
    prep_basis_kernel<<<(BDIM * IDIM) / 256, 256>>>(x);

    void *pA, *pB;
    cudaGetSymbolAddress(&pA, g_A);
    cudaGetSymbolAddress(&pB, g_B);

    PFN_encodeTiled enc = nullptr;
    cudaDriverEntryPointQueryResult qr;
    cudaGetDriverEntryPoint("cuTensorMapEncodeTiled", (void**)&enc, cudaEnableDefault, &qr);

    CUtensorMap mA, mB;
    encode_map(enc, &mA, pA, K9, BDIM, KB, BM);   // A: rows=b, box 64x128
    encode_map(enc, &mB, pB, K9, ODIM, KB, BN);   // B^T: rows=o, box 64x256

    cudaFuncSetAttribute(kan_hmma_kernel,
                         cudaFuncAttributeMaxDynamicSharedMemorySize, SMEM_BYTES);
    kan_hmma_kernel<<<dim3(ODIM / BN, BDIM / BM), NTHREADS, SMEM_BYTES>>>(mA, mB, y);
}

// round 15
// speedup vs baseline: 1.0669x; 1.0669x over previous
#include <cuda_runtime.h>
#include <cuda.h>
#include <cuda_fp16.h>
#include <math.h>
#include <stdint.h>

// ---------------- problem shape ----------------
#define BDIM 8192
#define IDIM 1024
#define ODIM 1024
#define ND   9
#define K9   (IDIM * ND)       // 9216

// ---------------- GEMM tiling ----------------
#define BM 128
#define BN 256
#define KB 64
#define NKB (K9 / KB)          // 144
#define NSTG 3
#define A_ST 16384             // 128 x 64 fp16
#define B_ST 32768             // 256 x 64 fp16
#define STG_BYTES (A_ST + B_ST)                  // 49152
#define SM_STAGE 1024
#define SMEM_BYTES (SM_STAGE + NSTG * STG_BYTES) // 148480
#define NTHREADS 288           // 8 consumer warps + 1 producer warp

// operand scaling (keeps fp16 operands in normal range)
#define SCALE_A 64.0f
#define SCALE_B 4096.0f
#define SCALE_OUT (1.0f / (SCALE_A * SCALE_B))

// ---------------- static device buffers ----------------
__device__ __half g_A[(size_t)BDIM * K9];   // [b][k], k = d*1024+i, scaled x64
__device__ __half g_B[(size_t)ODIM * K9];   // [o][k] (transposed), scaled x4096

// ---------------- PTX helpers ----------------
__device__ __forceinline__ uint32_t smem_u32(const void* p) {
    uint32_t a;
    asm("{ .reg .u64 t; cvta.to.shared.u64 t, %1; cvt.u32.u64 %0, t; }" : "=r"(a) : "l"(p));
    return a;
}
__device__ __forceinline__ void mbar_init(uint32_t m, uint32_t cnt) {
    asm volatile("mbarrier.init.shared.b64 [%0], %1;" :: "r"(m), "r"(cnt) : "memory");
}
__device__ __forceinline__ void mbar_expect_tx(uint32_t m, uint32_t bytes) {
    asm volatile("mbarrier.arrive.expect_tx.shared.b64 _, [%0], %1;" :: "r"(m), "r"(bytes) : "memory");
}
__device__ __forceinline__ void mbar_arrive(uint32_t m) {
    asm volatile("mbarrier.arrive.shared.b64 _, [%0];" :: "r"(m) : "memory");
}
__device__ __forceinline__ void mbar_wait(uint32_t m, uint32_t parity) {
    asm volatile(
        "{\n\t.reg .pred P;\n"
        "LW_%=:\n\t"
        "mbarrier.try_wait.parity.acquire.cta.shared::cta.b64 P, [%0], %1, 0x989680;\n\t"
        "@P bra.uni LD_%=;\n\t"
        "bra.uni LW_%=;\n"
        "LD_%=:\n\t}"
        :: "r"(m), "r"(parity) : "memory");
}
__device__ __forceinline__ void tma_2d(uint32_t dst, const void* map, int x, int y, uint32_t mbar) {
    asm volatile(
        "cp.async.bulk.tensor.2d.shared::cta.global.tile.mbarrier::complete_tx::bytes "
        "[%0], [%1, {%2, %3}], [%4];"
        :: "r"(dst), "l"(map), "r"(x), "r"(y), "r"(mbar) : "memory");
}
__device__ __forceinline__ void ldsm4(uint32_t* r, uint32_t a) {
    asm volatile("ldmatrix.sync.aligned.m8n8.x4.shared.b16 {%0,%1,%2,%3}, [%4];"
                 : "=r"(r[0]), "=r"(r[1]), "=r"(r[2]), "=r"(r[3]) : "r"(a));
}
__device__ __forceinline__ void mma16816(float* d, const uint32_t* a, const uint32_t* b) {
    asm volatile(
        "mma.sync.aligned.m16n8k16.row.col.f32.f16.f16.f32 "
        "{%0,%1,%2,%3}, {%4,%5,%6,%7}, {%8,%9}, {%0,%1,%2,%3};"
        : "+f"(d[0]), "+f"(d[1]), "+f"(d[2]), "+f"(d[3])
        : "r"(a[0]), "r"(a[1]), "r"(a[2]), "r"(a[3]), "r"(b[0]), "r"(b[1]));
}
// SW128 swizzle (matches CU_TENSOR_MAP_SWIZZLE_128B for 128B rows)
__device__ __forceinline__ uint32_t swz(uint32_t off) { return off ^ ((off >> 3) & 0x70); }

// ---------------- prep kernels ----------------
__global__ void prep_basis_kernel(const float* __restrict__ x) {
    int idx = blockIdx.x * blockDim.x + threadIdx.x;
    int b = idx >> 10;
    int i = idx & 1023;
    const float S = 5.1231056256176605f;    // sqrt(17)+1
    const float PIQ = 0.7511255444649425f;  // pi^-1/4
    const float SQ2 = 1.4142135623730951f;
    const float ha[9] = {0.f, 0.f, 1.0f, 0.8164965809f, 0.7071067812f,
                         0.6324555320f, 0.5773502692f, 0.5345224838f, 0.5f};
    const float hb[9] = {0.f, 0.f, 0.7071067812f, 0.8164965809f, 0.8660254038f,
                         0.8944271910f, 0.9128709292f, 0.9258200998f, 0.9354143467f};
    float t = tanhf(x[idx]) * S;
    float g = expf(-0.5f * t * t);
    float h[ND];
    h[0] = PIQ * g;
    h[1] = SQ2 * t * h[0];
#pragma unroll
    for (int d = 2; d < ND; ++d) h[d] = ha[d] * t * h[d - 1] - hb[d] * h[d - 2];
    size_t base = (size_t)b * K9 + i;
#pragma unroll
    for (int d = 0; d < ND; ++d)
        g_A[base + (size_t)d * 1024] = __float2half_rn(h[d] * SCALE_A);
}

// c[i][o][d] -> g_B[o][d*1024+i], coalesced both sides via 32x32x9 smem tile
__global__ __launch_bounds__(256)
void prep_w_kernel(const float* __restrict__ c) {
    __shared__ float s[32][289];
    int i0 = blockIdx.x * 32;
    int o0 = blockIdx.y * 32;
    for (int j = threadIdx.x; j < 32 * 72; j += 256) {
        int i = j / 72, q = j - (j / 72) * 72;
        float4 v = *(const float4*)(c + ((size_t)(i0 + i) * 1024 + o0) * 9 + q * 4);
        s[i][q * 4 + 0] = v.x; s[i][q * 4 + 1] = v.y;
        s[i][q * 4 + 2] = v.z; s[i][q * 4 + 3] = v.w;
    }
    __syncthreads();
    int lane = threadIdx.x & 31, w = threadIdx.x >> 5;
    for (int col = w; col < 288; col += 8) {
        int o = col / 9, d = col - o * 9;
        g_B[(size_t)(o0 + o) * K9 + d * 1024 + i0 + lane] =
            __float2half_rn(s[lane][col] * SCALE_B);
    }
}

// ---------------- TMA-fed HMMA GEMM ----------------
// 9 warps: 0-7 consumers (2x4 warp grid, warp tile 64x64), warp 8 = TMA producer.
__global__ __launch_bounds__(NTHREADS, 1)
void kan_hmma_kernel(const __grid_constant__ CUtensorMap tmA,
                     const __grid_constant__ CUtensorMap tmB,
                     float* __restrict__ y) {
    extern __shared__ __align__(1024) char smem[];
    const uint32_t sb = smem_u32(smem);
    const int tid = threadIdx.x;
    const int wid = tid >> 5;
    const int lane = tid & 31;
    const int rowBase = blockIdx.y * BM;
    const int colBase = blockIdx.x * BN;
    const uint32_t FULL = sb, EMPTY = sb + 24;

    if (tid == 0) {
        for (int s = 0; s < NSTG; ++s) {
            mbar_init(FULL + s * 8, 1);      // producer expect_tx arrival
            mbar_init(EMPTY + s * 8, 8);     // one elected lane per consumer warp
        }
    }
    __syncthreads();

    if (wid == 8) {
        // ---- producer ----
        if (lane == 0) {
            uint32_t stg = 0, pe = 1;
            for (int kb = 0; kb < NKB; ++kb) {
                mbar_wait(EMPTY + stg * 8, pe);
                uint32_t fb = FULL + stg * 8;
                mbar_expect_tx(fb, STG_BYTES);
                uint32_t s0 = sb + SM_STAGE + stg * STG_BYTES;
                tma_2d(s0,        &tmA, kb * KB, rowBase, fb);
                tma_2d(s0 + A_ST, &tmB, kb * KB, colBase, fb);
                if (++stg == NSTG) { stg = 0; pe ^= 1; }
            }
        }
        return;
    }

    // ---- consumers: warp tile 64(M) x 64(N) ----
    const int wm = wid & 1;          // 2 warp-rows of 64
    const int wn = wid >> 1;         // 4 warp-cols of 64

    float acc[4][8][4];
#pragma unroll
    for (int a = 0; a < 4; ++a)
#pragma unroll
        for (int b = 0; b < 8; ++b)
#pragma unroll
            for (int q = 0; q < 4; ++q) acc[a][b][q] = 0.0f;

    // ldsm lane offsets
    // A (row-major [m][k]): x4 = m0-7/k0-7, m8-15/k0-7, m0-7/k8-15, m8-15/k8-15
    const uint32_t aRow = wm * 64 + (lane & 15);
    const uint32_t aCol = (lane >> 4) * 16;
    // B (non-trans on [n][k]): x4 = n0-7/k0-7, n0-7/k8-15, n8-15/k0-7, n8-15/k8-15
    const uint32_t q2 = lane >> 3;
    const uint32_t bRow = wn * 64 + (lane & 7) + (q2 >> 1) * 8;
    const uint32_t bCol = (q2 & 1) * 16;

    uint32_t stg = 0, pf = 0;
    for (int kb = 0; kb < NKB; ++kb) {
        mbar_wait(FULL + stg * 8, pf);
        const uint32_t sA = sb + SM_STAGE + stg * STG_BYTES;
        const uint32_t sB = sA + A_ST;

#pragma unroll
        for (int ks = 0; ks < 4; ++ks) {
            uint32_t aF[4][4];
#pragma unroll
            for (int mt = 0; mt < 4; ++mt)
                ldsm4(aF[mt], sA + swz((aRow + mt * 16) * 128 + ks * 32 + aCol));
#pragma unroll
            for (int ng = 0; ng < 4; ++ng) {
                uint32_t bF[4];
                ldsm4(bF, sB + swz((bRow + ng * 16) * 128 + ks * 32 + bCol));
#pragma unroll
                for (int mt = 0; mt < 4; ++mt) {
                    mma16816(acc[mt][ng * 2],     aF[mt], &bF[0]);
                    mma16816(acc[mt][ng * 2 + 1], aF[mt], &bF[2]);
                }
            }
        }
        __syncwarp();
        if (lane == 0) mbar_arrive(EMPTY + stg * 8);
        if (++stg == NSTG) { stg = 0; pf ^= 1; }
    }

    // epilogue: scale back, store
    const float SC = SCALE_OUT;
#pragma unroll
    for (int mt = 0; mt < 4; ++mt) {
#pragma unroll
        for (int n8 = 0; n8 < 8; ++n8) {
            int r0 = rowBase + wm * 64 + mt * 16 + (lane >> 2);
            int c0 = colBase + wn * 64 + n8 * 8 + (lane & 3) * 2;
            *(float2*)&y[(size_t)r0 * ODIM + c0] =
                make_float2(acc[mt][n8][0] * SC, acc[mt][n8][1] * SC);
            *(float2*)&y[(size_t)(r0 + 8) * ODIM + c0] =
                make_float2(acc[mt][n8][2] * SC, acc[mt][n8][3] * SC);
        }
    }
}

// ---------------- host ----------------
typedef CUresult (*PFN_encodeTiled)(CUtensorMap*, CUtensorMapDataType, cuuint32_t, void*,
                                    const cuuint64_t*, const cuuint64_t*, const cuuint32_t*,
                                    const cuuint32_t*, CUtensorMapInterleave, CUtensorMapSwizzle,
                                    CUtensorMapL2promotion, CUtensorMapFloatOOBfill);

static void encode_map(PFN_encodeTiled enc, CUtensorMap* m, void* ptr,
                       uint64_t d0, uint64_t d1, uint32_t b0, uint32_t b1) {
    cuuint64_t dims[2] = {d0, d1};
    cuuint64_t strides[1] = {d0 * sizeof(__half)};
    cuuint32_t box[2] = {b0, b1};
    cuuint32_t es[2] = {1, 1};
    enc(m, CU_TENSOR_MAP_DATA_TYPE_FLOAT16, 2, ptr, dims, strides, box, es,
        CU_TENSOR_MAP_INTERLEAVE_NONE, CU_TENSOR_MAP_SWIZZLE_128B,
        CU_TENSOR_MAP_L2_PROMOTION_L2_128B, CU_TENSOR_MAP_FLOAT_OOB_FILL_NONE);
}

extern "C" void kernel_launch(void* const* d_in, const int* in_sizes, int n_in,
                              void* d_out, int out_size) {
    const float* x = (const float*)d_in[0];
    const float* c = (const float*)d_in[1];
    if (n_in >= 2 && in_sizes[0] == K9 * ODIM) {   // coeffs first? swap
        const float* t = x; x = c; c = t;
    }
    float* y = (float*)d_out;

    prep_w_kernel<<<dim3(IDIM / 32, ODIM / 32), 256>>>(c);
    prep_basis_kernel<<<(BDIM * IDIM) / 256, 256>>>(x);

    void *pA, *pB;
    cudaGetSymbolAddress(&pA, g_A);
    cudaGetSymbolAddress(&pB, g_B);

    PFN_encodeTiled enc = nullptr;
    cudaDriverEntryPointQueryResult qr;
    cudaGetDriverEntryPoint("cuTensorMapEncodeTiled", (void**)&enc, cudaEnableDefault, &qr);

    CUtensorMap mA, mB;
    encode_map(enc, &mA, pA, K9, BDIM, KB, BM);   // A: rows=b, box 64x128
    encode_map(enc, &mB, pB, K9, ODIM, KB, BN);   // B^T: rows=o, box 64x256

    cudaFuncSetAttribute(kan_hmma_kernel,
                         cudaFuncAttributeMaxDynamicSharedMemorySize, SMEM_BYTES);
    kan_hmma_kernel<<<dim3(ODIM / BN, BDIM / BM), NTHREADS, SMEM_BYTES>>>(mA, mB, y);
}